// round 16
// baseline (speedup 1.0000x reference)
#include <cuda_runtime.h>
#include <cuda_fp16.h>
#include <cstdint>

// Problem constants
#define BB 8
#define SEQ 1024
#define CC 512
#define NH 8
#define HD 64
#define NG 32
#define GSZ 16
#define C3 1536

// Scratch
__device__ __half g_xn_h[BB * SEQ * CC];      // normalized x (fp16)
__device__ __half g_qkv_h[BB * SEQ * C3];     // qkv projection (fp16)
__device__ __half g_attn_h[BB * SEQ * CC];    // attention output (fp16)
__device__ __half g_wh_qkv[CC * C3];          // w_qkv [K,N] fp16
__device__ __half g_wh_out[CC * CC];          // w_out [K,N] fp16
__device__ __half g_po[(size_t)2 * BB * NH * SEQ * HD];  // per-split normalized o
__device__ float2 g_ml[2 * BB * NH * SEQ];    // per-split (m, l)

// ---------------------------------------------------------------------------
// helpers
// ---------------------------------------------------------------------------
__device__ __forceinline__ uint32_t smem_u32(const void* p) {
    uint32_t a; asm("{ .reg .u64 t; cvta.to.shared.u64 t, %1; cvt.u32.u64 %0, t; }" : "=r"(a) : "l"(p));
    return a;
}
__device__ __forceinline__ uint32_t ex2h2(float a, float b) {
    __half2 h = __floats2half2_rn(a, b);
    uint32_t u = *reinterpret_cast<uint32_t*>(&h);
    uint32_t r; asm("ex2.approx.f16x2 %0, %1;" : "=r"(r) : "r"(u));
    return r;
}

#define CP_ASYNC16(sa, ga) \
    asm volatile("cp.async.cg.shared.global [%0], [%1], 16;" :: "r"(sa), "l"(ga))
#define CP_COMMIT() asm volatile("cp.async.commit_group;")
#define CP_WAIT(n)  asm volatile("cp.async.wait_group %0;" :: "n"(n))

#define LDMATRIX_X4(r0, r1, r2, r3, addr) \
    asm volatile("ldmatrix.sync.aligned.m8n8.x4.shared.b16 {%0,%1,%2,%3}, [%4];" \
        : "=r"(r0), "=r"(r1), "=r"(r2), "=r"(r3) : "r"(addr))

#define LDMATRIX_X4_T(r0, r1, r2, r3, addr) \
    asm volatile("ldmatrix.sync.aligned.m8n8.x4.trans.shared.b16 {%0,%1,%2,%3}, [%4];" \
        : "=r"(r0), "=r"(r1), "=r"(r2), "=r"(r3) : "r"(addr))

#define MMA16816(c, a0, a1, a2, a3, b0, b1) \
    asm volatile("mma.sync.aligned.m16n8k16.row.col.f32.f16.f16.f32 " \
        "{%0,%1,%2,%3}, {%4,%5,%6,%7}, {%8,%9}, {%0,%1,%2,%3};" \
        : "+f"((c)[0]), "+f"((c)[1]), "+f"((c)[2]), "+f"((c)[3]) \
        : "r"(a0), "r"(a1), "r"(a2), "r"(a3), "r"(b0), "r"(b1))

// ---------------------------------------------------------------------------
// Kernel 0: both weight converts in ONE launch
// ---------------------------------------------------------------------------
#define NQKV (CC * C3)
#define NOUT (CC * CC)

__global__ __launch_bounds__(256) void wconv_kernel(
    const float* __restrict__ Wq, __half* __restrict__ Whq,
    const float* __restrict__ Wo, __half* __restrict__ Who)
{
    int i = (blockIdx.x * 256 + threadIdx.x) * 4;
    if (i < NQKV) {
        float4 v = *reinterpret_cast<const float4*>(Wq + i);
        __half2* o = reinterpret_cast<__half2*>(Whq + i);
        o[0] = __floats2half2_rn(v.x, v.y);
        o[1] = __floats2half2_rn(v.z, v.w);
    } else {
        int j = i - NQKV;
        if (j < NOUT) {
            float4 v = *reinterpret_cast<const float4*>(Wo + j);
            __half2* o = reinterpret_cast<__half2*>(Who + j);
            o[0] = __floats2half2_rn(v.x, v.y);
            o[1] = __floats2half2_rn(v.z, v.w);
        }
    }
}

// ---------------------------------------------------------------------------
// Kernel 1: GroupNorm -> fp16. Quad-coalesced.
// ---------------------------------------------------------------------------
__global__ __launch_bounds__(256) void gn_kernel(
    const float* __restrict__ x, const float* __restrict__ gamma,
    const float* __restrict__ beta, __half* __restrict__ xn)
{
    int bg = blockIdx.x;
    int b = bg >> 5, g = bg & 31;
    const float* base = x + (size_t)b * SEQ * CC + g * GSZ;
    int tid = threadIdx.x;
    int q4 = tid & 3;
    int sbase = tid >> 2;

    float sum = 0.f, sq = 0.f;
    #pragma unroll
    for (int i = 0; i < 16; i++) {
        int s = sbase + i * 64;
        float4 v = *reinterpret_cast<const float4*>(base + (size_t)s * CC + q4 * 4);
        sum += v.x + v.y + v.z + v.w;
        sq  += v.x * v.x + v.y * v.y + v.z * v.z + v.w * v.w;
    }
    #pragma unroll
    for (int off = 16; off; off >>= 1) {
        sum += __shfl_xor_sync(0xFFFFFFFFu, sum, off);
        sq  += __shfl_xor_sync(0xFFFFFFFFu, sq, off);
    }
    __shared__ float red[2][8];
    __shared__ float stats[2];
    int wid = tid >> 5, lid = tid & 31;
    if (lid == 0) { red[0][wid] = sum; red[1][wid] = sq; }
    __syncthreads();
    if (tid == 0) {
        float S = 0.f, Q = 0.f;
        #pragma unroll
        for (int w = 0; w < 8; w++) { S += red[0][w]; Q += red[1][w]; }
        float mu = S * (1.f / 16384.f);
        float var = Q * (1.f / 16384.f) - mu * mu;
        stats[0] = mu;
        stats[1] = rsqrtf(var + 1e-6f);
    }
    __syncthreads();
    float mu = stats[0], rstd = stats[1];

    float ga[4], be[4];
    #pragma unroll
    for (int c = 0; c < 4; c++) {
        ga[c] = gamma[g * GSZ + q4 * 4 + c] * rstd;
        be[c] = beta[g * GSZ + q4 * 4 + c];
    }
    __half* obase = xn + (size_t)b * SEQ * CC + g * GSZ;
    #pragma unroll
    for (int i = 0; i < 16; i++) {
        int s = sbase + i * 64;
        float4 v = *reinterpret_cast<const float4*>(base + (size_t)s * CC + q4 * 4);
        float y0 = (v.x - mu) * ga[0] + be[0];
        float y1 = (v.y - mu) * ga[1] + be[1];
        float y2 = (v.z - mu) * ga[2] + be[2];
        float y3 = (v.w - mu) * ga[3] + be[3];
        __half2* q = reinterpret_cast<__half2*>(obase + (size_t)s * CC + q4 * 4);
        q[0] = __floats2half2_rn(y0, y1);
        q[1] = __floats2half2_rn(y2, y3);
    }
}

// ---------------------------------------------------------------------------
// Kernel 2: fp16 HMMA GEMM. Tile 64x128, BK=32, 128 threads, 4-slot ring,
// 3 CTAs/SM (unchanged R15 WIN).
// ---------------------------------------------------------------------------
#define ASTR 40
#define BSTR 136
#define AHALVES (64 * ASTR)
#define BHALVES (32 * BSTR)
#define GSLOT (AHALVES + BHALVES)
#define GEMM_SMEM (4 * GSLOT * 2)

template<bool HOUT>
__global__ __launch_bounds__(128, 3) void gemm_hmma(
    const __half* __restrict__ A, const __half* __restrict__ W,
    const float* __restrict__ bias, const float* __restrict__ R,
    void* __restrict__ Cv, int N)
{
    extern __shared__ __half dsm[];

    int tid = threadIdx.x;
    int lane = tid & 31;
    int wid = tid >> 5;
    int wm = (wid & 1) * 32;
    int wn = (wid >> 1) * 64;
    int bm = blockIdx.y * 64;
    int bn = blockIdx.x * 128;

    float c[2][8][4];
    #pragma unroll
    for (int mi = 0; mi < 2; mi++)
        #pragma unroll
        for (int ni = 0; ni < 8; ni++)
            #pragma unroll
            for (int k = 0; k < 4; k++) c[mi][ni][k] = 0.f;

    auto stage = [&](int s, int slot) {
        __half* Ad = dsm + slot * GSLOT;
        __half* Bd = Ad + AHALVES;
        #pragma unroll
        for (int i = 0; i < 2; i++) {
            int chunk = tid + i * 128;
            int r = chunk >> 2, c8 = (chunk & 3) * 8;
            CP_ASYNC16(smem_u32(&Ad[r * ASTR + c8]),
                       A + (size_t)(bm + r) * 512 + s * 32 + c8);
        }
        #pragma unroll
        for (int i = 0; i < 4; i++) {
            int chunk = tid + i * 128;
            int r = chunk >> 4, c8 = (chunk & 15) * 8;
            CP_ASYNC16(smem_u32(&Bd[r * BSTR + c8]),
                       W + (size_t)(s * 32 + r) * N + bn + c8);
        }
    };

    stage(0, 0); CP_COMMIT();
    stage(1, 1); CP_COMMIT();
    stage(2, 2); CP_COMMIT();

    #pragma unroll 4
    for (int s = 0; s < 16; s++) {
        int rem = 15 - s;
        if (rem >= 2)      CP_WAIT(2);
        else if (rem == 1) CP_WAIT(1);
        else               CP_WAIT(0);
        __syncthreads();
        if (s + 3 < 16) { stage(s + 3, (s + 3) & 3); CP_COMMIT(); }

        const __half* Ab = dsm + (s & 3) * GSLOT;
        const __half* Bb = Ab + AHALVES;
        #pragma unroll
        for (int kk = 0; kk < 2; kk++) {
            uint32_t a[2][4];
            #pragma unroll
            for (int mi = 0; mi < 2; mi++) {
                int row = wm + mi * 16 + (lane & 7) + ((lane >> 3) & 1) * 8;
                int kc = kk * 16 + ((lane >> 4) & 1) * 8;
                LDMATRIX_X4(a[mi][0], a[mi][1], a[mi][2], a[mi][3],
                            smem_u32(&Ab[row * ASTR + kc]));
            }
            uint32_t b[8][2];
            #pragma unroll
            for (int bi = 0; bi < 4; bi++) {
                int row = kk * 16 + ((lane >> 3) & 1) * 8 + (lane & 7);
                int col = wn + bi * 16 + (lane >> 4) * 8;
                uint32_t v0, v1, v2, v3;
                LDMATRIX_X4_T(v0, v1, v2, v3, smem_u32(&Bb[row * BSTR + col]));
                b[bi * 2 + 0][0] = v0; b[bi * 2 + 0][1] = v1;
                b[bi * 2 + 1][0] = v2; b[bi * 2 + 1][1] = v3;
            }
            #pragma unroll
            for (int mi = 0; mi < 2; mi++)
                #pragma unroll
                for (int ni = 0; ni < 8; ni++)
                    MMA16816(c[mi][ni], a[mi][0], a[mi][1], a[mi][2], a[mi][3],
                             b[ni][0], b[ni][1]);
        }
    }

    #pragma unroll
    for (int mi = 0; mi < 2; mi++) {
        int r0 = bm + wm + mi * 16 + (lane >> 2);
        #pragma unroll
        for (int ni = 0; ni < 8; ni++) {
            int col = bn + wn + ni * 8 + (lane & 3) * 2;
            float bx = bias[col], by = bias[col + 1];
            float v00 = c[mi][ni][0] + bx, v01 = c[mi][ni][1] + by;
            float v10 = c[mi][ni][2] + bx, v11 = c[mi][ni][3] + by;
            if (HOUT) {
                __half* C = (__half*)Cv;
                *reinterpret_cast<__half2*>(C + (size_t)r0 * N + col) = __floats2half2_rn(v00, v01);
                *reinterpret_cast<__half2*>(C + (size_t)(r0 + 8) * N + col) = __floats2half2_rn(v10, v11);
            } else {
                float* C = (float*)Cv;
                if (R) {
                    const float2 ra = *reinterpret_cast<const float2*>(R + (size_t)r0 * N + col);
                    const float2 rb = *reinterpret_cast<const float2*>(R + (size_t)(r0 + 8) * N + col);
                    v00 += ra.x; v01 += ra.y; v10 += rb.x; v11 += rb.y;
                }
                *reinterpret_cast<float2*>(C + (size_t)r0 * N + col) = make_float2(v00, v01);
                *reinterpret_cast<float2*>(C + (size_t)(r0 + 8) * N + col) = make_float2(v10, v11);
            }
        }
    }
}

// ---------------------------------------------------------------------------
// Kernel 3: HMMA flash attention, SPLIT-KV (2 splits of 8 chunks each).
// 64 q-rows per CTA, 128 threads, 3-slot KV ring, 3 CTAs/SM.
// Emits per-split l-normalized o (fp16) + (m, l) for the combine pass.
// ---------------------------------------------------------------------------
#define KSTR 72
#define AQHALVES (64 * KSTR)
#define KVSLOT  (2 * 64 * KSTR)
#define ATTN_SMEM ((AQHALVES + 3 * KVSLOT) * 2)

__global__ __launch_bounds__(128, 3) void attn_hmma(
    const __half* __restrict__ qkv, __half* __restrict__ po, float2* __restrict__ ml)
{
    extern __shared__ __half dsm[];
    __half* Qs = dsm;

    int z = blockIdx.z;
    int b = z >> 1, split = z & 1;
    int h = blockIdx.y, qt = blockIdx.x;
    int tid = threadIdx.x, lane = tid & 31, wid = tid >> 5;

    const __half* base = qkv + (size_t)b * SEQ * C3 + h * HD;

    auto kslot = [&](int slot) -> __half* { return dsm + AQHALVES + slot * KVSLOT; };

    auto stageKV = [&](int gc, int slot) {   // gc = global chunk index
        __half* Kd = kslot(slot);
        __half* Vd = Kd + 64 * KSTR;
        #pragma unroll
        for (int i = 0; i < 4; i++) {
            int chunk = tid + i * 128;
            int r = chunk >> 3, c8 = (chunk & 7) * 8;
            const __half* kg = base + (size_t)(gc * 64 + r) * C3 + CC + c8;
            CP_ASYNC16(smem_u32(&Kd[r * KSTR + c8]), kg);
            CP_ASYNC16(smem_u32(&Vd[r * KSTR + c8]), kg + CC);
        }
    };

    // stage Q (64 rows x 64 halves = 512 x 16B chunks, 4/thread)
    #pragma unroll
    for (int i = 0; i < 4; i++) {
        int chunk = tid + i * 128;
        int r = chunk >> 3, c8 = (chunk & 7) * 8;
        CP_ASYNC16(smem_u32(&Qs[r * KSTR + c8]),
                   base + (size_t)(qt * 64 + r) * C3 + c8);
    }
    int cbase = split * 8;
    stageKV(cbase + 0, 0); CP_COMMIT();
    stageKV(cbase + 1, 1); CP_COMMIT();

    float o[8][4];
    #pragma unroll
    for (int i = 0; i < 8; i++)
        #pragma unroll
        for (int k = 0; k < 4; k++) o[i][k] = 0.f;
    float cl[4] = {0.f, 0.f, 0.f, 0.f};
    float mrow0 = -1e30f, mrow1 = -1e30f;
    uint32_t qf[4][4];
    const uint32_t ONE2 = 0x3C003C00u;

    #pragma unroll
    for (int ch = 0; ch < 8; ch++) {
        if (ch < 7) CP_WAIT(1);
        else        CP_WAIT(0);
        __syncthreads();
        if (ch + 2 < 8) { stageKV(cbase + ch + 2, (ch + 2) % 3); CP_COMMIT(); }

        const __half* Kb = kslot(ch % 3);
        const __half* Vb = Kb + 64 * KSTR;

        if (ch == 0) {
            #pragma unroll
            for (int ks = 0; ks < 4; ks++) {
                int row = wid * 16 + (lane & 7) + ((lane >> 3) & 1) * 8;
                int col = ks * 16 + ((lane >> 4) & 1) * 8;
                LDMATRIX_X4(qf[ks][0], qf[ks][1], qf[ks][2], qf[ks][3],
                            smem_u32(&Qs[row * KSTR + col]));
            }
        }

        // ---- S = Q @ K^T ----
        float sacc[8][4];
        #pragma unroll
        for (int j = 0; j < 8; j++)
            #pragma unroll
            for (int k = 0; k < 4; k++) sacc[j][k] = 0.f;

        #pragma unroll
        for (int j = 0; j < 8; j++) {
            uint32_t kf[8];
            uint32_t a0 = smem_u32(&Kb[(8 * j + (lane & 7)) * KSTR + (lane >> 3) * 8]);
            LDMATRIX_X4(kf[0], kf[1], kf[2], kf[3], a0);
            LDMATRIX_X4(kf[4], kf[5], kf[6], kf[7], a0 + 64);
            #pragma unroll
            for (int ks = 0; ks < 4; ks++)
                MMA16816(sacc[j], qf[ks][0], qf[ks][1], qf[ks][2], qf[ks][3],
                         kf[2 * ks], kf[2 * ks + 1]);
        }

        // ---- online softmax (log2 domain, log2e/64 folded) ----
        const float sc = 1.4426950408889634f / 64.0f;
        #pragma unroll
        for (int j = 0; j < 8; j++)
            #pragma unroll
            for (int k = 0; k < 4; k++) sacc[j][k] *= sc;

        float mx0 = mrow0, mx1 = mrow1;
        #pragma unroll
        for (int j = 0; j < 8; j++) {
            mx0 = fmaxf(mx0, fmaxf(sacc[j][0], sacc[j][1]));
            mx1 = fmaxf(mx1, fmaxf(sacc[j][2], sacc[j][3]));
        }
        mx0 = fmaxf(mx0, __shfl_xor_sync(0xFFFFFFFFu, mx0, 1));
        mx0 = fmaxf(mx0, __shfl_xor_sync(0xFFFFFFFFu, mx0, 2));
        mx1 = fmaxf(mx1, __shfl_xor_sync(0xFFFFFFFFu, mx1, 1));
        mx1 = fmaxf(mx1, __shfl_xor_sync(0xFFFFFFFFu, mx1, 2));

        float corr0 = exp2f(mrow0 - mx0);
        float corr1 = exp2f(mrow1 - mx1);
        mrow0 = mx0; mrow1 = mx1;
        #pragma unroll
        for (int nd = 0; nd < 8; nd++) {
            o[nd][0] *= corr0; o[nd][1] *= corr0;
            o[nd][2] *= corr1; o[nd][3] *= corr1;
        }
        cl[0] *= corr0; cl[2] *= corr1;

        uint32_t pf[4][4];
        #pragma unroll
        for (int jp = 0; jp < 4; jp++) {
            pf[jp][0] = ex2h2(sacc[2 * jp][0] - mx0, sacc[2 * jp][1] - mx0);
            pf[jp][1] = ex2h2(sacc[2 * jp][2] - mx1, sacc[2 * jp][3] - mx1);
            pf[jp][2] = ex2h2(sacc[2 * jp + 1][0] - mx0, sacc[2 * jp + 1][1] - mx0);
            pf[jp][3] = ex2h2(sacc[2 * jp + 1][2] - mx1, sacc[2 * jp + 1][3] - mx1);
        }

        // ---- O += P @ V ; l += P @ ones ----
        #pragma unroll
        for (int ks = 0; ks < 4; ks++) {
            MMA16816(cl, pf[ks][0], pf[ks][1], pf[ks][2], pf[ks][3], ONE2, ONE2);
            #pragma unroll
            for (int np = 0; np < 4; np++) {
                uint32_t v0, v1, v2, v3;
                int row = 16 * ks + ((lane >> 3) & 1) * 8 + (lane & 7);
                int col = np * 16 + (lane >> 4) * 8;
                LDMATRIX_X4_T(v0, v1, v2, v3, smem_u32(&Vb[row * KSTR + col]));
                MMA16816(o[2 * np], pf[ks][0], pf[ks][1], pf[ks][2], pf[ks][3], v0, v1);
                MMA16816(o[2 * np + 1], pf[ks][0], pf[ks][1], pf[ks][2], pf[ks][3], v2, v3);
            }
        }
    }

    // ---- finalize: per-split normalized o + (m, l) ----
    float inv0 = 1.0f / cl[0], inv1 = 1.0f / cl[2];

    int r0 = qt * 64 + wid * 16 + (lane >> 2);
    size_t row0 = ((size_t)(b * NH + h)) * SEQ + r0;
    __half* ob0 = po + (row0 * 2 + split) * HD;
    __half* ob1 = po + ((row0 + 8) * 2 + split) * HD;
    #pragma unroll
    for (int nd = 0; nd < 8; nd++) {
        int col = nd * 8 + (lane & 3) * 2;
        *reinterpret_cast<__half2*>(ob0 + col) =
            __floats2half2_rn(o[nd][0] * inv0, o[nd][1] * inv0);
        *reinterpret_cast<__half2*>(ob1 + col) =
            __floats2half2_rn(o[nd][2] * inv1, o[nd][3] * inv1);
    }
    if ((lane & 3) == 0) {
        ml[row0 * 2 + split] = make_float2(mrow0, cl[0]);
        ml[(row0 + 8) * 2 + split] = make_float2(mrow1, cl[2]);
    }
}

// ---------------------------------------------------------------------------
// Kernel 4: combine the two KV splits -> g_attn ([b][seq][c] layout).
// ---------------------------------------------------------------------------
__global__ __launch_bounds__(256) void combine_kernel(
    const __half* __restrict__ po, const float2* __restrict__ ml,
    __half* __restrict__ attn)
{
    int idx = blockIdx.x * 256 + threadIdx.x;     // B*NH*SEQ*8 threads
    int row = idx >> 3, seg = idx & 7;
    float2 m0 = ml[row * 2 + 0], m1 = ml[row * 2 + 1];
    float M = fmaxf(m0.x, m1.x);
    float a0 = exp2f(m0.x - M) * m0.y;
    float a1 = exp2f(m1.x - M) * m1.y;
    float inv = 1.0f / (a0 + a1);
    float w0 = a0 * inv, w1 = a1 * inv;

    const __half2* p0 = reinterpret_cast<const __half2*>(po + ((size_t)row * 2 + 0) * HD + seg * 8);
    const __half2* p1 = reinterpret_cast<const __half2*>(po + ((size_t)row * 2 + 1) * HD + seg * 8);

    int b = row >> 13;           // / (NH*SEQ) = 8192
    int h = (row >> 10) & 7;
    int s = row & 1023;
    __half2* o = reinterpret_cast<__half2*>(attn + ((size_t)(b * SEQ + s)) * CC + h * HD + seg * 8);

    #pragma unroll
    for (int i = 0; i < 4; i++) {
        float2 f0 = __half22float2(p0[i]);
        float2 f1 = __half22float2(p1[i]);
        o[i] = __floats2half2_rn(w0 * f0.x + w1 * f1.x, w0 * f0.y + w1 * f1.y);
    }
}

// ---------------------------------------------------------------------------
// Launch
// ---------------------------------------------------------------------------
extern "C" void kernel_launch(void* const* d_in, const int* in_sizes, int n_in,
                              void* d_out, int out_size)
{
    const float* x        = (const float*)d_in[0];
    const float* gn_scale = (const float*)d_in[1];
    const float* gn_bias  = (const float*)d_in[2];
    const float* w_qkv    = (const float*)d_in[3];
    const float* b_qkv    = (const float*)d_in[4];
    const float* w_out    = (const float*)d_in[5];
    const float* b_out    = (const float*)d_in[6];
    float* out            = (float*)d_out;

    __half* xn;   cudaGetSymbolAddress((void**)&xn,   g_xn_h);
    __half* qkv;  cudaGetSymbolAddress((void**)&qkv,  g_qkv_h);
    __half* attn; cudaGetSymbolAddress((void**)&attn, g_attn_h);
    __half* whq;  cudaGetSymbolAddress((void**)&whq,  g_wh_qkv);
    __half* who;  cudaGetSymbolAddress((void**)&who,  g_wh_out);
    __half* po;   cudaGetSymbolAddress((void**)&po,   g_po);
    float2* ml;   cudaGetSymbolAddress((void**)&ml,   g_ml);

    cudaFuncSetAttribute(gemm_hmma<true>,  cudaFuncAttributeMaxDynamicSharedMemorySize, GEMM_SMEM);
    cudaFuncSetAttribute(gemm_hmma<false>, cudaFuncAttributeMaxDynamicSharedMemorySize, GEMM_SMEM);
    cudaFuncSetAttribute(attn_hmma,        cudaFuncAttributeMaxDynamicSharedMemorySize, ATTN_SMEM);

    // 0) weight converts
    wconv_kernel<<<((NQKV + NOUT) / 4 + 255) / 256, 256>>>(w_qkv, whq, w_out, who);

    // 1) GroupNorm -> fp16
    gn_kernel<<<BB * NG, 256>>>(x, gn_scale, gn_bias, xn);

    // 2) QKV projection
    gemm_hmma<true><<<dim3(C3 / 128, (BB * SEQ) / 64), 128, GEMM_SMEM>>>(xn, whq, b_qkv, nullptr, qkv, C3);

    // 3) Attention, split-KV x2: grid (16, 8, 16)
    attn_hmma<<<dim3(SEQ / 64, NH, BB * 2), 128, ATTN_SMEM>>>(qkv, po, ml);

    // 3b) combine splits -> attn
    combine_kernel<<<(BB * NH * SEQ * 8) / 256, 256>>>(po, ml, attn);

    // 4) Output projection + bias + residual
    gemm_hmma<false><<<dim3(CC / 128, (BB * SEQ) / 64), 128, GEMM_SMEM>>>(attn, who, b_out, x, out, CC);
}

// round 17
// speedup vs baseline: 1.0319x; 1.0319x over previous
#include <cuda_runtime.h>
#include <cuda_fp16.h>
#include <cstdint>

// Problem constants
#define BB 8
#define SEQ 1024
#define CC 512
#define NH 8
#define HD 64
#define NG 32
#define GSZ 16
#define C3 1536

// Scratch
__device__ __half g_xn_h[BB * SEQ * CC];    // normalized x (fp16)
__device__ __half g_qkv_h[BB * SEQ * C3];   // qkv projection (fp16)
__device__ __half g_attn_h[BB * SEQ * CC];  // attention output (fp16)
__device__ __half g_wh_qkv[CC * C3];        // w_qkv [K,N] fp16
__device__ __half g_wh_out[CC * CC];        // w_out [K,N] fp16

// ---------------------------------------------------------------------------
// helpers
// ---------------------------------------------------------------------------
__device__ __forceinline__ uint32_t smem_u32(const void* p) {
    uint32_t a; asm("{ .reg .u64 t; cvta.to.shared.u64 t, %1; cvt.u32.u64 %0, t; }" : "=r"(a) : "l"(p));
    return a;
}
__device__ __forceinline__ uint32_t ex2h2(float a, float b) {
    __half2 h = __floats2half2_rn(a, b);
    uint32_t u = *reinterpret_cast<uint32_t*>(&h);
    uint32_t r; asm("ex2.approx.f16x2 %0, %1;" : "=r"(r) : "r"(u));
    return r;
}

#define CP_ASYNC16(sa, ga) \
    asm volatile("cp.async.cg.shared.global [%0], [%1], 16;" :: "r"(sa), "l"(ga))
#define CP_COMMIT() asm volatile("cp.async.commit_group;")
#define CP_WAIT(n)  asm volatile("cp.async.wait_group %0;" :: "n"(n))

#define LDMATRIX_X4(r0, r1, r2, r3, addr) \
    asm volatile("ldmatrix.sync.aligned.m8n8.x4.shared.b16 {%0,%1,%2,%3}, [%4];" \
        : "=r"(r0), "=r"(r1), "=r"(r2), "=r"(r3) : "r"(addr))

#define LDMATRIX_X4_T(r0, r1, r2, r3, addr) \
    asm volatile("ldmatrix.sync.aligned.m8n8.x4.trans.shared.b16 {%0,%1,%2,%3}, [%4];" \
        : "=r"(r0), "=r"(r1), "=r"(r2), "=r"(r3) : "r"(addr))

#define MMA16816(c, a0, a1, a2, a3, b0, b1) \
    asm volatile("mma.sync.aligned.m16n8k16.row.col.f32.f16.f16.f32 " \
        "{%0,%1,%2,%3}, {%4,%5,%6,%7}, {%8,%9}, {%0,%1,%2,%3};" \
        : "+f"((c)[0]), "+f"((c)[1]), "+f"((c)[2]), "+f"((c)[3]) \
        : "r"(a0), "r"(a1), "r"(a2), "r"(a3), "r"(b0), "r"(b1))

// ---------------------------------------------------------------------------
// Kernel 0+1 FUSED: blocks [0,256) do GroupNorm; blocks [256, 1280) convert
// both weight matrices to fp16 (independent work, one launch).
// ---------------------------------------------------------------------------
#define NQKV (CC * C3)
#define NOUT (CC * CC)
#define GN_BLOCKS (BB * NG)                       // 256
#define WCONV_BLOCKS (((NQKV + NOUT) / 4) / 256)  // 1024

__global__ __launch_bounds__(256) void prep_kernel(
    const float* __restrict__ x, const float* __restrict__ gamma,
    const float* __restrict__ beta, __half* __restrict__ xn,
    const float* __restrict__ Wq, __half* __restrict__ Whq,
    const float* __restrict__ Wo, __half* __restrict__ Who)
{
    int tid = threadIdx.x;
    if (blockIdx.x >= GN_BLOCKS) {
        // ---- weight convert ----
        int i = ((blockIdx.x - GN_BLOCKS) * 256 + tid) * 4;
        if (i < NQKV) {
            float4 v = *reinterpret_cast<const float4*>(Wq + i);
            __half2* o = reinterpret_cast<__half2*>(Whq + i);
            o[0] = __floats2half2_rn(v.x, v.y);
            o[1] = __floats2half2_rn(v.z, v.w);
        } else {
            int j = i - NQKV;
            if (j < NOUT) {
                float4 v = *reinterpret_cast<const float4*>(Wo + j);
                __half2* o = reinterpret_cast<__half2*>(Who + j);
                o[0] = __floats2half2_rn(v.x, v.y);
                o[1] = __floats2half2_rn(v.z, v.w);
            }
        }
        return;
    }
    // ---- GroupNorm (quad-coalesced) ----
    int bg = blockIdx.x;
    int b = bg >> 5, g = bg & 31;
    const float* base = x + (size_t)b * SEQ * CC + g * GSZ;
    int q4 = tid & 3;
    int sbase = tid >> 2;

    float sum = 0.f, sq = 0.f;
    #pragma unroll
    for (int i = 0; i < 16; i++) {
        int s = sbase + i * 64;
        float4 v = *reinterpret_cast<const float4*>(base + (size_t)s * CC + q4 * 4);
        sum += v.x + v.y + v.z + v.w;
        sq  += v.x * v.x + v.y * v.y + v.z * v.z + v.w * v.w;
    }
    #pragma unroll
    for (int off = 16; off; off >>= 1) {
        sum += __shfl_xor_sync(0xFFFFFFFFu, sum, off);
        sq  += __shfl_xor_sync(0xFFFFFFFFu, sq, off);
    }
    __shared__ float red[2][8];
    __shared__ float stats[2];
    int wid = tid >> 5, lid = tid & 31;
    if (lid == 0) { red[0][wid] = sum; red[1][wid] = sq; }
    __syncthreads();
    if (tid == 0) {
        float S = 0.f, Q = 0.f;
        #pragma unroll
        for (int w = 0; w < 8; w++) { S += red[0][w]; Q += red[1][w]; }
        float mu = S * (1.f / 16384.f);
        float var = Q * (1.f / 16384.f) - mu * mu;
        stats[0] = mu;
        stats[1] = rsqrtf(var + 1e-6f);
    }
    __syncthreads();
    float mu = stats[0], rstd = stats[1];

    float ga[4], be[4];
    #pragma unroll
    for (int c = 0; c < 4; c++) {
        ga[c] = gamma[g * GSZ + q4 * 4 + c] * rstd;
        be[c] = beta[g * GSZ + q4 * 4 + c];
    }
    __half* obase = xn + (size_t)b * SEQ * CC + g * GSZ;
    #pragma unroll
    for (int i = 0; i < 16; i++) {
        int s = sbase + i * 64;
        float4 v = *reinterpret_cast<const float4*>(base + (size_t)s * CC + q4 * 4);
        float y0 = (v.x - mu) * ga[0] + be[0];
        float y1 = (v.y - mu) * ga[1] + be[1];
        float y2 = (v.z - mu) * ga[2] + be[2];
        float y3 = (v.w - mu) * ga[3] + be[3];
        __half2* q = reinterpret_cast<__half2*>(obase + (size_t)s * CC + q4 * 4);
        q[0] = __floats2half2_rn(y0, y1);
        q[1] = __floats2half2_rn(y2, y3);
    }
}

// ---------------------------------------------------------------------------
// Kernel 2: fp16 HMMA GEMM. Tile 64x128, BK=32, 128 threads, 4-slot ring,
// 3 CTAs/SM (unchanged R15 WIN).
// ---------------------------------------------------------------------------
#define ASTR 40
#define BSTR 136
#define AHALVES (64 * ASTR)
#define BHALVES (32 * BSTR)
#define GSLOT (AHALVES + BHALVES)
#define GEMM_SMEM (4 * GSLOT * 2)

template<bool HOUT>
__global__ __launch_bounds__(128, 3) void gemm_hmma(
    const __half* __restrict__ A, const __half* __restrict__ W,
    const float* __restrict__ bias, const float* __restrict__ R,
    void* __restrict__ Cv, int N)
{
    extern __shared__ __half dsm[];

    int tid = threadIdx.x;
    int lane = tid & 31;
    int wid = tid >> 5;
    int wm = (wid & 1) * 32;
    int wn = (wid >> 1) * 64;
    int bm = blockIdx.y * 64;
    int bn = blockIdx.x * 128;

    float c[2][8][4];
    #pragma unroll
    for (int mi = 0; mi < 2; mi++)
        #pragma unroll
        for (int ni = 0; ni < 8; ni++)
            #pragma unroll
            for (int k = 0; k < 4; k++) c[mi][ni][k] = 0.f;

    auto stage = [&](int s, int slot) {
        __half* Ad = dsm + slot * GSLOT;
        __half* Bd = Ad + AHALVES;
        #pragma unroll
        for (int i = 0; i < 2; i++) {
            int chunk = tid + i * 128;
            int r = chunk >> 2, c8 = (chunk & 3) * 8;
            CP_ASYNC16(smem_u32(&Ad[r * ASTR + c8]),
                       A + (size_t)(bm + r) * 512 + s * 32 + c8);
        }
        #pragma unroll
        for (int i = 0; i < 4; i++) {
            int chunk = tid + i * 128;
            int r = chunk >> 4, c8 = (chunk & 15) * 8;
            CP_ASYNC16(smem_u32(&Bd[r * BSTR + c8]),
                       W + (size_t)(s * 32 + r) * N + bn + c8);
        }
    };

    stage(0, 0); CP_COMMIT();
    stage(1, 1); CP_COMMIT();
    stage(2, 2); CP_COMMIT();

    #pragma unroll 4
    for (int s = 0; s < 16; s++) {
        int rem = 15 - s;
        if (rem >= 2)      CP_WAIT(2);
        else if (rem == 1) CP_WAIT(1);
        else               CP_WAIT(0);
        __syncthreads();
        if (s + 3 < 16) { stage(s + 3, (s + 3) & 3); CP_COMMIT(); }

        const __half* Ab = dsm + (s & 3) * GSLOT;
        const __half* Bb = Ab + AHALVES;
        #pragma unroll
        for (int kk = 0; kk < 2; kk++) {
            uint32_t a[2][4];
            #pragma unroll
            for (int mi = 0; mi < 2; mi++) {
                int row = wm + mi * 16 + (lane & 7) + ((lane >> 3) & 1) * 8;
                int kc = kk * 16 + ((lane >> 4) & 1) * 8;
                LDMATRIX_X4(a[mi][0], a[mi][1], a[mi][2], a[mi][3],
                            smem_u32(&Ab[row * ASTR + kc]));
            }
            uint32_t b[8][2];
            #pragma unroll
            for (int bi = 0; bi < 4; bi++) {
                int row = kk * 16 + ((lane >> 3) & 1) * 8 + (lane & 7);
                int col = wn + bi * 16 + (lane >> 4) * 8;
                uint32_t v0, v1, v2, v3;
                LDMATRIX_X4_T(v0, v1, v2, v3, smem_u32(&Bb[row * BSTR + col]));
                b[bi * 2 + 0][0] = v0; b[bi * 2 + 0][1] = v1;
                b[bi * 2 + 1][0] = v2; b[bi * 2 + 1][1] = v3;
            }
            #pragma unroll
            for (int mi = 0; mi < 2; mi++)
                #pragma unroll
                for (int ni = 0; ni < 8; ni++)
                    MMA16816(c[mi][ni], a[mi][0], a[mi][1], a[mi][2], a[mi][3],
                             b[ni][0], b[ni][1]);
        }
    }

    #pragma unroll
    for (int mi = 0; mi < 2; mi++) {
        int r0 = bm + wm + mi * 16 + (lane >> 2);
        #pragma unroll
        for (int ni = 0; ni < 8; ni++) {
            int col = bn + wn + ni * 8 + (lane & 3) * 2;
            float bx = bias[col], by = bias[col + 1];
            float v00 = c[mi][ni][0] + bx, v01 = c[mi][ni][1] + by;
            float v10 = c[mi][ni][2] + bx, v11 = c[mi][ni][3] + by;
            if (HOUT) {
                __half* C = (__half*)Cv;
                *reinterpret_cast<__half2*>(C + (size_t)r0 * N + col) = __floats2half2_rn(v00, v01);
                *reinterpret_cast<__half2*>(C + (size_t)(r0 + 8) * N + col) = __floats2half2_rn(v10, v11);
            } else {
                float* C = (float*)Cv;
                if (R) {
                    const float2 ra = *reinterpret_cast<const float2*>(R + (size_t)r0 * N + col);
                    const float2 rb = *reinterpret_cast<const float2*>(R + (size_t)(r0 + 8) * N + col);
                    v00 += ra.x; v01 += ra.y; v10 += rb.x; v11 += rb.y;
                }
                *reinterpret_cast<float2*>(C + (size_t)r0 * N + col) = make_float2(v00, v01);
                *reinterpret_cast<float2*>(C + (size_t)(r0 + 8) * N + col) = make_float2(v10, v11);
            }
        }
    }
}

// ---------------------------------------------------------------------------
// Kernel 3: HMMA flash attention (R15 winner shape: 64 q-rows, 16 chunks,
// 3-slot KV ring, 3 CTAs/SM) with the chunk loop FULLY unrolled so the
// ch%3 slot indices const-fold.
// ---------------------------------------------------------------------------
#define KSTR 72
#define AQHALVES (64 * KSTR)
#define KVSLOT  (2 * 64 * KSTR)
#define ATTN_SMEM ((AQHALVES + 3 * KVSLOT) * 2)

__global__ __launch_bounds__(128, 3) void attn_hmma(
    const __half* __restrict__ qkv, __half* __restrict__ out)
{
    extern __shared__ __half dsm[];
    __half* Qs = dsm;

    int b = blockIdx.z, h = blockIdx.y, qt = blockIdx.x;
    int tid = threadIdx.x, lane = tid & 31, wid = tid >> 5;

    const __half* base = qkv + (size_t)b * SEQ * C3 + h * HD;

    auto kslot = [&](int slot) -> __half* { return dsm + AQHALVES + slot * KVSLOT; };

    auto stageKV = [&](int c, int slot) {
        __half* Kd = kslot(slot);
        __half* Vd = Kd + 64 * KSTR;
        #pragma unroll
        for (int i = 0; i < 4; i++) {
            int chunk = tid + i * 128;
            int r = chunk >> 3, c8 = (chunk & 7) * 8;
            const __half* kg = base + (size_t)(c * 64 + r) * C3 + CC + c8;
            CP_ASYNC16(smem_u32(&Kd[r * KSTR + c8]), kg);
            CP_ASYNC16(smem_u32(&Vd[r * KSTR + c8]), kg + CC);
        }
    };

    // stage Q (64 rows x 64 halves = 512 x 16B chunks, 4/thread)
    #pragma unroll
    for (int i = 0; i < 4; i++) {
        int chunk = tid + i * 128;
        int r = chunk >> 3, c8 = (chunk & 7) * 8;
        CP_ASYNC16(smem_u32(&Qs[r * KSTR + c8]),
                   base + (size_t)(qt * 64 + r) * C3 + c8);
    }
    stageKV(0, 0); CP_COMMIT();
    stageKV(1, 1); CP_COMMIT();

    float o[8][4];
    #pragma unroll
    for (int i = 0; i < 8; i++)
        #pragma unroll
        for (int k = 0; k < 4; k++) o[i][k] = 0.f;
    float cl[4] = {0.f, 0.f, 0.f, 0.f};
    float mrow0 = -1e30f, mrow1 = -1e30f;
    uint32_t qf[4][4];
    const uint32_t ONE2 = 0x3C003C00u;

    #pragma unroll
    for (int ch = 0; ch < 16; ch++) {
        if (ch < 15) CP_WAIT(1);
        else         CP_WAIT(0);
        __syncthreads();
        if (ch + 2 < 16) { stageKV(ch + 2, (ch + 2) % 3); CP_COMMIT(); }

        const __half* Kb = kslot(ch % 3);
        const __half* Vb = Kb + 64 * KSTR;

        if (ch == 0) {
            #pragma unroll
            for (int ks = 0; ks < 4; ks++) {
                int row = wid * 16 + (lane & 7) + ((lane >> 3) & 1) * 8;
                int col = ks * 16 + ((lane >> 4) & 1) * 8;
                LDMATRIX_X4(qf[ks][0], qf[ks][1], qf[ks][2], qf[ks][3],
                            smem_u32(&Qs[row * KSTR + col]));
            }
        }

        // ---- S = Q @ K^T ----
        float sacc[8][4];
        #pragma unroll
        for (int j = 0; j < 8; j++)
            #pragma unroll
            for (int k = 0; k < 4; k++) sacc[j][k] = 0.f;

        #pragma unroll
        for (int j = 0; j < 8; j++) {
            uint32_t kf[8];
            uint32_t a0 = smem_u32(&Kb[(8 * j + (lane & 7)) * KSTR + (lane >> 3) * 8]);
            LDMATRIX_X4(kf[0], kf[1], kf[2], kf[3], a0);
            LDMATRIX_X4(kf[4], kf[5], kf[6], kf[7], a0 + 64);
            #pragma unroll
            for (int ks = 0; ks < 4; ks++)
                MMA16816(sacc[j], qf[ks][0], qf[ks][1], qf[ks][2], qf[ks][3],
                         kf[2 * ks], kf[2 * ks + 1]);
        }

        // ---- online softmax (log2 domain, log2e/64 folded) ----
        const float sc = 1.4426950408889634f / 64.0f;
        #pragma unroll
        for (int j = 0; j < 8; j++)
            #pragma unroll
            for (int k = 0; k < 4; k++) sacc[j][k] *= sc;

        float mx0 = mrow0, mx1 = mrow1;
        #pragma unroll
        for (int j = 0; j < 8; j++) {
            mx0 = fmaxf(mx0, fmaxf(sacc[j][0], sacc[j][1]));
            mx1 = fmaxf(mx1, fmaxf(sacc[j][2], sacc[j][3]));
        }
        mx0 = fmaxf(mx0, __shfl_xor_sync(0xFFFFFFFFu, mx0, 1));
        mx0 = fmaxf(mx0, __shfl_xor_sync(0xFFFFFFFFu, mx0, 2));
        mx1 = fmaxf(mx1, __shfl_xor_sync(0xFFFFFFFFu, mx1, 1));
        mx1 = fmaxf(mx1, __shfl_xor_sync(0xFFFFFFFFu, mx1, 2));

        float corr0 = exp2f(mrow0 - mx0);
        float corr1 = exp2f(mrow1 - mx1);
        mrow0 = mx0; mrow1 = mx1;
        #pragma unroll
        for (int nd = 0; nd < 8; nd++) {
            o[nd][0] *= corr0; o[nd][1] *= corr0;
            o[nd][2] *= corr1; o[nd][3] *= corr1;
        }
        cl[0] *= corr0; cl[2] *= corr1;

        uint32_t pf[4][4];
        #pragma unroll
        for (int jp = 0; jp < 4; jp++) {
            pf[jp][0] = ex2h2(sacc[2 * jp][0] - mx0, sacc[2 * jp][1] - mx0);
            pf[jp][1] = ex2h2(sacc[2 * jp][2] - mx1, sacc[2 * jp][3] - mx1);
            pf[jp][2] = ex2h2(sacc[2 * jp + 1][0] - mx0, sacc[2 * jp + 1][1] - mx0);
            pf[jp][3] = ex2h2(sacc[2 * jp + 1][2] - mx1, sacc[2 * jp + 1][3] - mx1);
        }

        // ---- O += P @ V ; l += P @ ones ----
        #pragma unroll
        for (int ks = 0; ks < 4; ks++) {
            MMA16816(cl, pf[ks][0], pf[ks][1], pf[ks][2], pf[ks][3], ONE2, ONE2);
            #pragma unroll
            for (int np = 0; np < 4; np++) {
                uint32_t v0, v1, v2, v3;
                int row = 16 * ks + ((lane >> 3) & 1) * 8 + (lane & 7);
                int col = np * 16 + (lane >> 4) * 8;
                LDMATRIX_X4_T(v0, v1, v2, v3, smem_u32(&Vb[row * KSTR + col]));
                MMA16816(o[2 * np], pf[ks][0], pf[ks][1], pf[ks][2], pf[ks][3], v0, v1);
                MMA16816(o[2 * np + 1], pf[ks][0], pf[ks][1], pf[ks][2], pf[ks][3], v2, v3);
            }
        }
    }

    // ---- finalize ----
    float inv0 = 1.0f / cl[0], inv1 = 1.0f / cl[2];

    int r0 = qt * 64 + wid * 16 + (lane >> 2);
    __half* ob = out + (size_t)b * SEQ * CC + h * HD;
    #pragma unroll
    for (int nd = 0; nd < 8; nd++) {
        int col = nd * 8 + (lane & 3) * 2;
        *reinterpret_cast<__half2*>(ob + (size_t)r0 * CC + col) =
            __floats2half2_rn(o[nd][0] * inv0, o[nd][1] * inv0);
        *reinterpret_cast<__half2*>(ob + (size_t)(r0 + 8) * CC + col) =
            __floats2half2_rn(o[nd][2] * inv1, o[nd][3] * inv1);
    }
}

// ---------------------------------------------------------------------------
// Launch
// ---------------------------------------------------------------------------
extern "C" void kernel_launch(void* const* d_in, const int* in_sizes, int n_in,
                              void* d_out, int out_size)
{
    const float* x        = (const float*)d_in[0];
    const float* gn_scale = (const float*)d_in[1];
    const float* gn_bias  = (const float*)d_in[2];
    const float* w_qkv    = (const float*)d_in[3];
    const float* b_qkv    = (const float*)d_in[4];
    const float* w_out    = (const float*)d_in[5];
    const float* b_out    = (const float*)d_in[6];
    float* out            = (float*)d_out;

    __half* xn;   cudaGetSymbolAddress((void**)&xn,   g_xn_h);
    __half* qkv;  cudaGetSymbolAddress((void**)&qkv,  g_qkv_h);
    __half* attn; cudaGetSymbolAddress((void**)&attn, g_attn_h);
    __half* whq;  cudaGetSymbolAddress((void**)&whq,  g_wh_qkv);
    __half* who;  cudaGetSymbolAddress((void**)&who,  g_wh_out);

    cudaFuncSetAttribute(gemm_hmma<true>,  cudaFuncAttributeMaxDynamicSharedMemorySize, GEMM_SMEM);
    cudaFuncSetAttribute(gemm_hmma<false>, cudaFuncAttributeMaxDynamicSharedMemorySize, GEMM_SMEM);
    cudaFuncSetAttribute(attn_hmma,        cudaFuncAttributeMaxDynamicSharedMemorySize, ATTN_SMEM);

    // 0+1) fused: GroupNorm + both weight converts
    prep_kernel<<<GN_BLOCKS + WCONV_BLOCKS, 256>>>(
        x, gn_scale, gn_bias, xn, w_qkv, whq, w_out, who);

    // 2) QKV projection
    gemm_hmma<true><<<dim3(C3 / 128, (BB * SEQ) / 64), 128, GEMM_SMEM>>>(xn, whq, b_qkv, nullptr, qkv, C3);

    // 3) Attention (64 q-rows per CTA, full 16-chunk loop)
    attn_hmma<<<dim3(SEQ / 64, NH, BB), 128, ATTN_SMEM>>>(qkv, attn);

    // 4) Output projection + bias + residual
    gemm_hmma<false><<<dim3(CC / 128, (BB * SEQ) / 64), 128, GEMM_SMEM>>>(attn, who, b_out, x, out, CC);
}